// round 15
// baseline (speedup 1.0000x reference)
#include <cuda_runtime.h>
#include <cuda_fp16.h>
#include <cuda_bf16.h>
#include <cstdint>

#define N_STARS 2048
#define BATCH   256
#define PF      28
#define NGE     512
#define GF      32
#define KTOT    60        // PF + GF
#define KPAD    64        // zero-padded K for MMA
#define OPD2    65536     // 256*256

// Scratch (no device allocation allowed -> __device__ globals)
__device__ float g_W[KTOT * BATCH];   // W[k][b], k-major

// ---------------------------------------------------------------------------
// Stage 1: index search + W construction (unchanged; passing since R3)
// ---------------------------------------------------------------------------
__global__ __launch_bounds__(256) void prep_kernel(
    const float* __restrict__ positions, const float* __restrict__ obs_pos,
    const float* __restrict__ poly_dic,  const float* __restrict__ graph_dic,
    const float* __restrict__ alpha_poly,const float* __restrict__ alpha_graph)
{
    int b = blockIdx.x;
    int t = threadIdx.x;

    __shared__ int   s_min;
    __shared__ float s_row[NGE];
    __shared__ float s_prow[PF];
    __shared__ float s_part[8][32];

    if (t == 0) s_min = N_STARS;
    __syncthreads();

    float px = positions[2 * b], py = positions[2 * b + 1];
    int local = N_STARS;
    for (int n = t; n < N_STARS; n += 256) {
        float ox = obs_pos[2 * n], oy = obs_pos[2 * n + 1];
        if (ox == px || oy == py) { local = n; break; }
    }
    if (local < N_STARS) atomicMin(&s_min, local);
    __syncthreads();
    int idx = (s_min < N_STARS) ? s_min : 0;

    for (int g = t; g < NGE; g += 256) s_row[g] = graph_dic[(size_t)idx * NGE + g];
    if (t < PF) s_prow[t] = poly_dic[(size_t)idx * PF + t];
    __syncthreads();

    {
        int kg = t & 31, sl = t >> 5;
        float acc = 0.f;
        int g0 = sl * 64;
        #pragma unroll 8
        for (int i = 0; i < 64; i++) {
            int g = g0 + i;
            acc += s_row[g] * alpha_graph[g * GF + kg];
        }
        s_part[sl][kg] = acc;
    }
    __syncthreads();

    if (t < GF) {
        float acc = 0.f;
        #pragma unroll
        for (int sl = 0; sl < 8; sl++) acc += s_part[sl][t];
        g_W[(PF + t) * BATCH + b] = acc;
    } else if (t < GF + PF) {
        int k = t - GF;
        float acc = 0.f;
        #pragma unroll
        for (int p = 0; p < PF; p++) acc += s_prow[p] * alpha_poly[p * PF + k];
        g_W[k * BATCH + b] = acc;
    }
}

// ---------------------------------------------------------------------------
// Stage 2: C[b][e] = sum_k W[b][k] * S[k][e] via mma.sync m16n8k16 fp16,
// hi/lo split (lo scaled x4096), dual fp32 accumulators -> ~1e-6 accuracy.
// CTA tile 64b x 128e, 8 warps (2b x 4e), warp tile 32b x 32e.
// smem: half2 (k-pair) tiles [kp][x], strides 136/72 u32 -> bank-perfect
// ((8*tg + g) mod 32 permutation). Every fragment register = one LDS.32.
// ---------------------------------------------------------------------------
#define S_STRIDE 136          // u32 (half2) per kp row: 128 e + 8 pad
#define W_STRIDE 72           // u32 per kp row: 64 b + 8 pad
#define OFF_SH  0
#define OFF_SL  (32 * S_STRIDE)               // 4352
#define OFF_WH  (2 * 32 * S_STRIDE)           // 8704
#define OFF_WL  (OFF_WH + 32 * W_STRIDE)      // 11008
#define SMEM_U32 (OFF_WL + 32 * W_STRIDE)     // 13312
#define SMEM_BYTES (SMEM_U32 * 4)             // 53248

__device__ __forceinline__ void mma_f16(float* d, const uint32_t* a, const uint32_t* b) {
    asm volatile(
        "mma.sync.aligned.m16n8k16.row.col.f32.f16.f16.f32 "
        "{%0,%1,%2,%3}, {%4,%5,%6,%7}, {%8,%9}, {%0,%1,%2,%3};"
        : "+f"(d[0]), "+f"(d[1]), "+f"(d[2]), "+f"(d[3])
        : "r"(a[0]), "r"(a[1]), "r"(a[2]), "r"(a[3]), "r"(b[0]), "r"(b[1]));
}
__device__ __forceinline__ void split_h(float v, __half& h, __half& l) {
    h = __float2half_rn(v);
    l = __float2half_rn((v - __half2float(h)) * 4096.0f);   // exact scale; lo stays normal
}

__global__ void __launch_bounds__(256, 2) mccd_mma(
    const float* __restrict__ S_poly, const float* __restrict__ S_graph,
    float* __restrict__ out)
{
    extern __shared__ uint32_t smem[];
    __half* hs = reinterpret_cast<__half*>(smem);

    int tid    = threadIdx.x;
    int e_base = blockIdx.x * 128;
    int b_base = blockIdx.y * 64;

    // ---- stage: read fp32 (coalesced float4), split hi/lo, store half tiles ----
    {
        int l4 = (tid & 31) * 4;
        int kw = tid >> 5;
        #pragma unroll
        for (int kk = kw; kk < KPAD; kk += 8) {
            int kp = kk >> 1, par = kk & 1;
            // S tile: 128 e per k-row
            float4 sv = make_float4(0.f, 0.f, 0.f, 0.f);
            if (kk < PF)
                sv = *reinterpret_cast<const float4*>(&S_poly[(size_t)kk * OPD2 + e_base + l4]);
            else if (kk < KTOT)
                sv = *reinterpret_cast<const float4*>(&S_graph[(size_t)(kk - PF) * OPD2 + e_base + l4]);
            const float vs[4] = { sv.x, sv.y, sv.z, sv.w };
            #pragma unroll
            for (int i = 0; i < 4; i++) {
                __half h, l; split_h(vs[i], h, l);
                int ix = (kp * S_STRIDE + l4 + i) * 2 + par;
                hs[OFF_SH * 2 + ix] = h;
                hs[OFF_SL * 2 + ix] = l;
            }
            // W tile: 64 b per k-row (lanes with l4 < 64)
            if (l4 < 64) {
                float4 wv = make_float4(0.f, 0.f, 0.f, 0.f);
                if (kk < KTOT)
                    wv = *reinterpret_cast<const float4*>(&g_W[kk * BATCH + b_base + l4]);
                const float vw[4] = { wv.x, wv.y, wv.z, wv.w };
                #pragma unroll
                for (int i = 0; i < 4; i++) {
                    __half h, l; split_h(vw[i], h, l);
                    int ix = (kp * W_STRIDE + l4 + i) * 2 + par;
                    hs[OFF_WH * 2 + ix] = h;
                    hs[OFF_WL * 2 + ix] = l;
                }
            }
        }
    }
    __syncthreads();

    int lane = tid & 31, w = tid >> 5;
    int g  = lane >> 2;               // 0..7
    int tg = lane & 3;                // 0..3
    int bo = (w & 1) * 32;            // warp b-offset
    int eo = (w >> 1) * 32;           // warp e-offset

    const uint32_t* Sh = smem + OFF_SH;
    const uint32_t* Sl = smem + OFF_SL;
    const uint32_t* Wh = smem + OFF_WH;
    const uint32_t* Wl = smem + OFF_WL;

    float acc_h[2][4][4] = {};        // hi*hi
    float acc_m[2][4][4] = {};        // hi*lo + lo*hi  (x4096 scale)

    #pragma unroll
    for (int kt = 0; kt < 4; kt++) {
        int r0 = 8 * kt + tg;                       // kp row (k = 2*kp, 2*kp+1)
        const uint32_t* wh0 = Wh + r0 * W_STRIDE + bo + g;
        const uint32_t* wh4 = wh0 + 4 * W_STRIDE;
        const uint32_t* wl0 = Wl + r0 * W_STRIDE + bo + g;
        const uint32_t* wl4 = wl0 + 4 * W_STRIDE;
        const uint32_t* sh0 = Sh + r0 * S_STRIDE + eo + g;
        const uint32_t* sh4 = sh0 + 4 * S_STRIDE;
        const uint32_t* sl0 = Sl + r0 * S_STRIDE + eo + g;
        const uint32_t* sl4 = sl0 + 4 * S_STRIDE;

        uint32_t ah[2][4], al[2][4];
        #pragma unroll
        for (int mt = 0; mt < 2; mt++) {
            int o = 16 * mt;
            ah[mt][0] = wh0[o]; ah[mt][1] = wh0[o + 8];
            ah[mt][2] = wh4[o]; ah[mt][3] = wh4[o + 8];
            al[mt][0] = wl0[o]; al[mt][1] = wl0[o + 8];
            al[mt][2] = wl4[o]; al[mt][3] = wl4[o + 8];
        }
        uint32_t bh[4][2], bl[4][2];
        #pragma unroll
        for (int nt = 0; nt < 4; nt++) {
            bh[nt][0] = sh0[8 * nt]; bh[nt][1] = sh4[8 * nt];
            bl[nt][0] = sl0[8 * nt]; bl[nt][1] = sl4[8 * nt];
        }
        #pragma unroll
        for (int mt = 0; mt < 2; mt++)
            #pragma unroll
            for (int nt = 0; nt < 4; nt++) {
                mma_f16(acc_h[mt][nt], ah[mt], bh[nt]);
                mma_f16(acc_m[mt][nt], ah[mt], bl[nt]);
                mma_f16(acc_m[mt][nt], al[mt], bh[nt]);
            }
    }

    // ---- epilogue: combine scales, float2 stores ----
    const float inv = 1.0f / 4096.0f;
    #pragma unroll
    for (int mt = 0; mt < 2; mt++) {
        #pragma unroll
        for (int nt = 0; nt < 4; nt++) {
            size_t b = (size_t)(b_base + bo + 16 * mt + g);
            size_t e = (size_t)(e_base + eo + 8 * nt + 2 * tg);
            float f0 = acc_h[mt][nt][0] + acc_m[mt][nt][0] * inv;
            float f1 = acc_h[mt][nt][1] + acc_m[mt][nt][1] * inv;
            float f2 = acc_h[mt][nt][2] + acc_m[mt][nt][2] * inv;
            float f3 = acc_h[mt][nt][3] + acc_m[mt][nt][3] * inv;
            *reinterpret_cast<float2*>(&out[b * OPD2 + e])       = make_float2(f0, f1);
            *reinterpret_cast<float2*>(&out[(b + 8) * OPD2 + e]) = make_float2(f2, f3);
        }
    }
}

// ---------------------------------------------------------------------------
extern "C" void kernel_launch(void* const* d_in, const int* in_sizes, int n_in,
                              void* d_out, int out_size) {
    const float* positions   = (const float*)d_in[0];
    const float* obs_pos     = (const float*)d_in[1];
    const float* poly_dic    = (const float*)d_in[2];
    const float* graph_dic   = (const float*)d_in[3];
    const float* alpha_poly  = (const float*)d_in[4];
    const float* alpha_graph = (const float*)d_in[5];
    const float* S_poly      = (const float*)d_in[6];
    const float* S_graph     = (const float*)d_in[7];
    float* out = (float*)d_out;

    cudaFuncSetAttribute(mccd_mma, cudaFuncAttributeMaxDynamicSharedMemorySize,
                         SMEM_BYTES);

    prep_kernel<<<BATCH, 256>>>(positions, obs_pos, poly_dic, graph_dic,
                                alpha_poly, alpha_graph);
    mccd_mma<<<dim3(OPD2 / 128, BATCH / 64), 256, SMEM_BYTES>>>(S_poly, S_graph, out);
}

// round 16
// speedup vs baseline: 1.6564x; 1.6564x over previous
#include <cuda_runtime.h>
#include <cuda_fp16.h>
#include <cuda_bf16.h>
#include <cstdint>

#define N_STARS 2048
#define BATCH   256
#define PF      28
#define NGE     512
#define GF      32
#define KTOT    60        // PF + GF
#define KPAD    64        // zero-padded K for MMA
#define OPD2    65536     // 256*256

// Scratch (no device allocation allowed -> __device__ globals)
__device__ float g_W[KTOT * BATCH];   // W[k][b], k-major

// ---------------------------------------------------------------------------
// Stage 1: index search + W construction (unchanged; passing since R3)
// ---------------------------------------------------------------------------
__global__ __launch_bounds__(256) void prep_kernel(
    const float* __restrict__ positions, const float* __restrict__ obs_pos,
    const float* __restrict__ poly_dic,  const float* __restrict__ graph_dic,
    const float* __restrict__ alpha_poly,const float* __restrict__ alpha_graph)
{
    int b = blockIdx.x;
    int t = threadIdx.x;

    __shared__ int   s_min;
    __shared__ float s_row[NGE];
    __shared__ float s_prow[PF];
    __shared__ float s_part[8][32];

    if (t == 0) s_min = N_STARS;
    __syncthreads();

    float px = positions[2 * b], py = positions[2 * b + 1];
    int local = N_STARS;
    for (int n = t; n < N_STARS; n += 256) {
        float ox = obs_pos[2 * n], oy = obs_pos[2 * n + 1];
        if (ox == px || oy == py) { local = n; break; }
    }
    if (local < N_STARS) atomicMin(&s_min, local);
    __syncthreads();
    int idx = (s_min < N_STARS) ? s_min : 0;

    for (int g = t; g < NGE; g += 256) s_row[g] = graph_dic[(size_t)idx * NGE + g];
    if (t < PF) s_prow[t] = poly_dic[(size_t)idx * PF + t];
    __syncthreads();

    {
        int kg = t & 31, sl = t >> 5;
        float acc = 0.f;
        int g0 = sl * 64;
        #pragma unroll 8
        for (int i = 0; i < 64; i++) {
            int g = g0 + i;
            acc += s_row[g] * alpha_graph[g * GF + kg];
        }
        s_part[sl][kg] = acc;
    }
    __syncthreads();

    if (t < GF) {
        float acc = 0.f;
        #pragma unroll
        for (int sl = 0; sl < 8; sl++) acc += s_part[sl][t];
        g_W[(PF + t) * BATCH + b] = acc;
    } else if (t < GF + PF) {
        int k = t - GF;
        float acc = 0.f;
        #pragma unroll
        for (int p = 0; p < PF; p++) acc += s_prow[p] * alpha_poly[p * PF + k];
        g_W[k * BATCH + b] = acc;
    }
}

// ---------------------------------------------------------------------------
// Stage 2: C[b][e] = sum_k W[b][k] * S[k][e] via mma.sync m16n8k16 fp16.
// hi/lo split with S pre-scaled by 2^22 -> h and l both NORMAL fp16 at the
// SAME scale, so hh + hl + lh all accumulate into ONE fp32 accumulator;
// epilogue multiplies by 2^-22. Dropped ll term ~2^-22 rel.
// CTA tile 128e x 128b (grid 1024), 8 warps (4b x 2e), warp tile 32b x 64e.
// smem: half2 k-pair tiles [kp][x], stride 136 u32 -> staging STS.128
// conflict-free; fragment LDS.32 bank-perfect ((8*tg+g) mod 32 permutation).
// ---------------------------------------------------------------------------
#define TSTRIDE 136                            // u32 per kp row (128 + 8 pad)
#define OFF_SH  0
#define OFF_SL  (32 * TSTRIDE)                 // 4352
#define OFF_WH  (2 * 32 * TSTRIDE)             // 8704
#define OFF_WL  (3 * 32 * TSTRIDE)             // 13056
#define SMEM_U32 (4 * 32 * TSTRIDE)            // 17408
#define SMEM_BYTES (SMEM_U32 * 4)              // 69632

#define S_SCALE 4194304.0f                     // 2^22
#define S_INV   (1.0f / 4194304.0f)

__device__ __forceinline__ void mma_f16(float* d, const uint32_t* a, const uint32_t* b) {
    asm volatile(
        "mma.sync.aligned.m16n8k16.row.col.f32.f16.f16.f32 "
        "{%0,%1,%2,%3}, {%4,%5,%6,%7}, {%8,%9}, {%0,%1,%2,%3};"
        : "+f"(d[0]), "+f"(d[1]), "+f"(d[2]), "+f"(d[3])
        : "r"(a[0]), "r"(a[1]), "r"(a[2]), "r"(a[3]), "r"(b[0]), "r"(b[1]));
}

// split x into h + l (both fp16, same scale); returns packed later by caller
__device__ __forceinline__ void split_h(float x, __half& h, __half& l) {
    h = __float2half_rn(x);
    l = __float2half_rn(x - __half2float(h));
}
__device__ __forceinline__ uint32_t packh(__half a, __half b) {
    __half2 p = __halves2half2(a, b);
    return *reinterpret_cast<uint32_t*>(&p);
}

__global__ void __launch_bounds__(256, 2) mccd_mma(
    const float* __restrict__ S_poly, const float* __restrict__ S_graph,
    float* __restrict__ out)
{
    extern __shared__ uint32_t smem[];

    int tid    = threadIdx.x;
    int e_base = blockIdx.x * 128;
    int b_base = blockIdx.y * 128;

    // ---- stage: fp32 float4 reads -> hi/lo half2 k-pair tiles, STS.128 ----
    {
        int x4 = (tid & 31) * 4;                    // 4 elements per lane
        #pragma unroll
        for (int p = 0; p < 4; p++) {
            int kp = (tid >> 5) + 8 * p;            // k-pair row 0..31
            int k0 = 2 * kp, k1 = 2 * kp + 1;
            // S rows (scaled by 2^22); k0/k1 never straddle PF (PF even)
            float4 s0 = make_float4(0.f, 0.f, 0.f, 0.f);
            float4 s1 = make_float4(0.f, 0.f, 0.f, 0.f);
            if (k0 < PF) {
                s0 = *reinterpret_cast<const float4*>(&S_poly[(size_t)k0 * OPD2 + e_base + x4]);
                s1 = *reinterpret_cast<const float4*>(&S_poly[(size_t)k1 * OPD2 + e_base + x4]);
            } else if (k0 < KTOT) {
                s0 = *reinterpret_cast<const float4*>(&S_graph[(size_t)(k0 - PF) * OPD2 + e_base + x4]);
                s1 = *reinterpret_cast<const float4*>(&S_graph[(size_t)(k1 - PF) * OPD2 + e_base + x4]);
            }
            float a0[4] = { s0.x, s0.y, s0.z, s0.w };
            float a1[4] = { s1.x, s1.y, s1.z, s1.w };
            uint4 hv, lv;
            uint32_t* hp = &hv.x; uint32_t* lp = &lv.x;
            #pragma unroll
            for (int i = 0; i < 4; i++) {
                __half h0, l0, h1, l1;
                split_h(a0[i] * S_SCALE, h0, l0);
                split_h(a1[i] * S_SCALE, h1, l1);
                hp[i] = packh(h0, h1);
                lp[i] = packh(l0, l1);
            }
            *reinterpret_cast<uint4*>(&smem[OFF_SH + kp * TSTRIDE + x4]) = hv;
            *reinterpret_cast<uint4*>(&smem[OFF_SL + kp * TSTRIDE + x4]) = lv;

            // W rows (unscaled)
            float4 w0 = make_float4(0.f, 0.f, 0.f, 0.f);
            float4 w1 = make_float4(0.f, 0.f, 0.f, 0.f);
            if (k0 < KTOT) {
                w0 = *reinterpret_cast<const float4*>(&g_W[k0 * BATCH + b_base + x4]);
                w1 = *reinterpret_cast<const float4*>(&g_W[k1 * BATCH + b_base + x4]);
            }
            float b0[4] = { w0.x, w0.y, w0.z, w0.w };
            float b1[4] = { w1.x, w1.y, w1.z, w1.w };
            #pragma unroll
            for (int i = 0; i < 4; i++) {
                __half h0, l0, h1, l1;
                split_h(b0[i], h0, l0);
                split_h(b1[i], h1, l1);
                hp[i] = packh(h0, h1);
                lp[i] = packh(l0, l1);
            }
            *reinterpret_cast<uint4*>(&smem[OFF_WH + kp * TSTRIDE + x4]) = hv;
            *reinterpret_cast<uint4*>(&smem[OFF_WL + kp * TSTRIDE + x4]) = lv;
        }
    }
    __syncthreads();

    int lane = tid & 31, w = tid >> 5;
    int g  = lane >> 2;               // 0..7
    int tg = lane & 3;                // 0..3
    int b0w = (w & 3) * 32;           // warp b-offset (4 b-warps)
    int e0w = (w >> 2) * 64;          // warp e-offset (2 e-warps)

    const uint32_t* Sh = smem + OFF_SH;
    const uint32_t* Sl = smem + OFF_SL;
    const uint32_t* Wh = smem + OFF_WH;
    const uint32_t* Wl = smem + OFF_WL;

    float acc[2][8][4] = {};          // single accumulator set (64 regs)

    #pragma unroll
    for (int kt = 0; kt < 4; kt++) {
        int r0 = (8 * kt + tg) * TSTRIDE;
        int r4 = r0 + 4 * TSTRIDE;

        // A fragments (W side): 2 m-tiles, hi + lo
        uint32_t ah[2][4], al[2][4];
        #pragma unroll
        for (int mt = 0; mt < 2; mt++) {
            int o = b0w + 16 * mt + g;
            ah[mt][0] = Wh[r0 + o]; ah[mt][1] = Wh[r0 + o + 8];
            ah[mt][2] = Wh[r4 + o]; ah[mt][3] = Wh[r4 + o + 8];
            al[mt][0] = Wl[r0 + o]; al[mt][1] = Wl[r0 + o + 8];
            al[mt][2] = Wl[r4 + o]; al[mt][3] = Wl[r4 + o + 8];
        }

        // B fragments (S side) in two halves of 4 n-tiles (register pressure)
        #pragma unroll
        for (int h = 0; h < 2; h++) {
            uint32_t bh[4][2], bl[4][2];
            #pragma unroll
            for (int q = 0; q < 4; q++) {
                int eo = e0w + (4 * h + q) * 8 + g;
                bh[q][0] = Sh[r0 + eo]; bh[q][1] = Sh[r4 + eo];
                bl[q][0] = Sl[r0 + eo]; bl[q][1] = Sl[r4 + eo];
            }
            #pragma unroll
            for (int mt = 0; mt < 2; mt++)
                #pragma unroll
                for (int q = 0; q < 4; q++) {
                    float* d = acc[mt][4 * h + q];
                    mma_f16(d, ah[mt], bh[q]);   // hh
                    mma_f16(d, ah[mt], bl[q]);   // hl  (same scale -> same acc)
                    mma_f16(d, al[mt], bh[q]);   // lh
                }
        }
    }

    // ---- epilogue: unscale (S was x2^22), float2 stores ----
    #pragma unroll
    for (int mt = 0; mt < 2; mt++) {
        #pragma unroll
        for (int nt = 0; nt < 8; nt++) {
            size_t b = (size_t)(b_base + b0w + 16 * mt + g);
            size_t e = (size_t)(e_base + e0w + 8 * nt + 2 * tg);
            float* d = acc[mt][nt];
            *reinterpret_cast<float2*>(&out[b * OPD2 + e])
                = make_float2(d[0] * S_INV, d[1] * S_INV);
            *reinterpret_cast<float2*>(&out[(b + 8) * OPD2 + e])
                = make_float2(d[2] * S_INV, d[3] * S_INV);
        }
    }
}

// ---------------------------------------------------------------------------
extern "C" void kernel_launch(void* const* d_in, const int* in_sizes, int n_in,
                              void* d_out, int out_size) {
    const float* positions   = (const float*)d_in[0];
    const float* obs_pos     = (const float*)d_in[1];
    const float* poly_dic    = (const float*)d_in[2];
    const float* graph_dic   = (const float*)d_in[3];
    const float* alpha_poly  = (const float*)d_in[4];
    const float* alpha_graph = (const float*)d_in[5];
    const float* S_poly      = (const float*)d_in[6];
    const float* S_graph     = (const float*)d_in[7];
    float* out = (float*)d_out;

    cudaFuncSetAttribute(mccd_mma, cudaFuncAttributeMaxDynamicSharedMemorySize,
                         SMEM_BYTES);

    prep_kernel<<<BATCH, 256>>>(positions, obs_pos, poly_dic, graph_dic,
                                alpha_poly, alpha_graph);
    mccd_mma<<<dim3(OPD2 / 128, BATCH / 128), 256, SMEM_BYTES>>>(S_poly, S_graph, out);
}